// round 3
// baseline (speedup 1.0000x reference)
#include <cuda_runtime.h>

#define BATCH 512
#define NPART 60
#define PDIM 20
#define SDIM 14
#define NVERT 5
#define HID 60
#define DE 20
#define DOUT 24
#define NQUAD 15                 // NPART / 4
#define NTILES (BATCH * NQUAD)   // 7680
#define THREADS 256

// -------- scratch (static device allocation: allowed) --------
__device__ float g_A  [BATCH * NPART * HID];   // fr receiver part + fr_b1
__device__ float g_Bv [BATCH * NPART * HID];   // fr sender part
__device__ float g_Apv[BATCH * NPART * HID];   // pv receiver part + pv_b1
__device__ float g_Cv [BATCH * NVERT * HID];   // pv vertex part
__device__ float g_Osum[NTILES * DOUT];        // per-tile O partial sums

// -------- shared memory layout (float offsets) --------
#define OFF_FRW2 0
#define OFF_FRW3 3600
#define OFF_PVW2 4800
#define OFF_PVW3 8400
#define OFF_FOW1 9600
#define OFF_FOW2 13200
#define OFF_FOW3 16800
#define OFF_FRB2 18240
#define OFF_FRB3 18300
#define OFF_PVB2 18320
#define OFF_PVB3 18380
#define OFF_FOB1 18400
#define OFF_FOB2 18460
#define OFF_FOB3 18520
#define OFF_A    18544   // 4*60
#define OFF_APV  18784   // 4*60
#define OFF_CV   19024   // 5*60
#define OFF_C    19324   // 4*60 : [x(20) | Ebar_pp(20) | Ebar_pv(20)] per receiver
#define OFF_H1S  19564   // 4*60
#define OFF_H2S  19804   // 4*60
#define OFF_O    20044   // 4*24 (pad to 96)
#define OFF_STG  20140   // 256*21 staging (stride 21 -> conflict-free)
#define SMEM_FLOATS (OFF_STG + 256 * 21)
#define SMEM_BYTES  (SMEM_FLOATS * 4)

// ============================================================
// Kernel 1: per-particle / per-vertex first-layer precompute
// ============================================================
__global__ void precompute_kernel(const float* __restrict__ x,
                                  const float* __restrict__ y,
                                  const float* __restrict__ fr_w1,
                                  const float* __restrict__ fr_b1,
                                  const float* __restrict__ pv_w1,
                                  const float* __restrict__ pv_b1)
{
    __shared__ float xb[PDIM * NPART];   // x[b] slice, layout [p][n]
    __shared__ float yb[SDIM * NVERT];   // y[b] slice, layout [s][v]
    const int b   = blockIdx.x;
    const int tid = threadIdx.x;

    for (int i = tid; i < PDIM * NPART; i += blockDim.x)
        xb[i] = x[(size_t)b * PDIM * NPART + i];
    for (int i = tid; i < SDIM * NVERT; i += blockDim.x)
        yb[i] = y[(size_t)b * SDIM * NVERT + i];
    __syncthreads();

    for (int idx = tid; idx < NPART * HID; idx += blockDim.x) {
        const int n = idx / HID;
        const int h = idx - n * HID;
        float a1 = fr_b1[h];
        float a2 = 0.0f;
        float a3 = pv_b1[h];
#pragma unroll
        for (int p = 0; p < PDIM; p++) {
            const float xv = xb[p * NPART + n];     // xt[b][n][p]
            a1 = fmaf(xv, fr_w1[p * HID + h], a1);
            a2 = fmaf(xv, fr_w1[(PDIM + p) * HID + h], a2);
            a3 = fmaf(xv, pv_w1[p * HID + h], a3);
        }
        const size_t o = (size_t)b * NPART * HID + idx;
        g_A[o]   = a1;
        g_Bv[o]  = a2;
        g_Apv[o] = a3;
    }

    for (int idx = tid; idx < NVERT * HID; idx += blockDim.x) {
        const int v = idx / HID;
        const int h = idx - v * HID;
        float a = 0.0f;
#pragma unroll
        for (int s = 0; s < SDIM; s++)
            a = fmaf(yb[s * NVERT + v], pv_w1[(PDIM + s) * HID + h], a);
        g_Cv[(size_t)b * NVERT * HID + idx] = a;
    }
}

// ============================================================
// MLP layers 2..3 (60->60->20, relu each), weights in SMEM
// ============================================================
__device__ __forceinline__ void mlp_tail(const float* __restrict__ sm,
                                         int w2o, int b2o, int w3o, int b3o,
                                         const float h1[HID], float e[DE])
{
    float h2[HID];
#pragma unroll
    for (int j = 0; j < HID; j++) h2[j] = sm[b2o + j];
#pragma unroll
    for (int k = 0; k < HID; k++) {
        const float a = h1[k];
        const float4* wr = reinterpret_cast<const float4*>(sm + w2o + k * HID);
#pragma unroll
        for (int j4 = 0; j4 < HID / 4; j4++) {
            const float4 w = wr[j4];
            h2[4 * j4 + 0] = fmaf(a, w.x, h2[4 * j4 + 0]);
            h2[4 * j4 + 1] = fmaf(a, w.y, h2[4 * j4 + 1]);
            h2[4 * j4 + 2] = fmaf(a, w.z, h2[4 * j4 + 2]);
            h2[4 * j4 + 3] = fmaf(a, w.w, h2[4 * j4 + 3]);
        }
    }
#pragma unroll
    for (int j = 0; j < HID; j++) h2[j] = fmaxf(h2[j], 0.0f);

#pragma unroll
    for (int j = 0; j < DE; j++) e[j] = sm[b3o + j];
#pragma unroll
    for (int k = 0; k < HID; k++) {
        const float a = h2[k];
        const float4* wr = reinterpret_cast<const float4*>(sm + w3o + k * DE);
#pragma unroll
        for (int j4 = 0; j4 < DE / 4; j4++) {
            const float4 w = wr[j4];
            e[4 * j4 + 0] = fmaf(a, w.x, e[4 * j4 + 0]);
            e[4 * j4 + 1] = fmaf(a, w.y, e[4 * j4 + 1]);
            e[4 * j4 + 2] = fmaf(a, w.z, e[4 * j4 + 2]);
            e[4 * j4 + 3] = fmaf(a, w.w, e[4 * j4 + 3]);
        }
    }
#pragma unroll
    for (int j = 0; j < DE; j++) e[j] = fmaxf(e[j], 0.0f);
}

__device__ __forceinline__ void smem_copy(float* dst, const float* __restrict__ src,
                                          int n, int tid)
{
    for (int i = tid; i < n; i += THREADS) dst[i] = src[i];
}

// ============================================================
// Kernel 2: persistent main kernel. Tile = (batch, 4 receivers)
// ============================================================
__global__ void __launch_bounds__(THREADS, 1)
main_kernel(const float* __restrict__ x,
            const float* __restrict__ fr_w2, const float* __restrict__ fr_b2,
            const float* __restrict__ fr_w3, const float* __restrict__ fr_b3,
            const float* __restrict__ pv_w2, const float* __restrict__ pv_b2,
            const float* __restrict__ pv_w3, const float* __restrict__ pv_b3,
            const float* __restrict__ fo_w1, const float* __restrict__ fo_b1,
            const float* __restrict__ fo_w2, const float* __restrict__ fo_b2,
            const float* __restrict__ fo_w3, const float* __restrict__ fo_b3)
{
    extern __shared__ float sm[];
    const int t = threadIdx.x;

    // --- load all weights once per block ---
    smem_copy(sm + OFF_FRW2, fr_w2, HID * HID, t);
    smem_copy(sm + OFF_FRW3, fr_w3, HID * DE, t);
    smem_copy(sm + OFF_PVW2, pv_w2, HID * HID, t);
    smem_copy(sm + OFF_PVW3, pv_w3, HID * DE, t);
    smem_copy(sm + OFF_FOW1, fo_w1, HID * HID, t);
    smem_copy(sm + OFF_FOW2, fo_w2, HID * HID, t);
    smem_copy(sm + OFF_FOW3, fo_w3, HID * DOUT, t);
    smem_copy(sm + OFF_FRB2, fr_b2, HID, t);
    smem_copy(sm + OFF_FRB3, fr_b3, DE, t);
    smem_copy(sm + OFF_PVB2, pv_b2, HID, t);
    smem_copy(sm + OFF_PVB3, pv_b3, DE, t);
    smem_copy(sm + OFF_FOB1, fo_b1, HID, t);
    smem_copy(sm + OFF_FOB2, fo_b2, HID, t);
    smem_copy(sm + OFF_FOB3, fo_b3, DOUT, t);
    __syncthreads();

    for (int tile = blockIdx.x; tile < NTILES; tile += gridDim.x) {
        const int b  = tile / NQUAD;
        const int q  = tile - b * NQUAD;
        const int r0 = q * 4;

        // --- stage per-tile inputs ---
        for (int i = t; i < 4 * HID; i += THREADS)
            sm[OFF_A + i] = g_A[((size_t)b * NPART + r0) * HID + i];
        for (int i = t; i < 4 * HID; i += THREADS)
            sm[OFF_APV + i] = g_Apv[((size_t)b * NPART + r0) * HID + i];
        for (int i = t; i < NVERT * HID; i += THREADS)
            sm[OFF_CV + i] = g_Cv[(size_t)b * NVERT * HID + i];
        // xt slice for the 4 receivers: sC[rl][p] = x[b, p, r0+rl]
        for (int i = t; i < 4 * PDIM; i += THREADS) {
            const int rl = i / PDIM;
            const int p  = i - rl * PDIM;
            sm[OFF_C + rl * HID + p] =
                x[(size_t)b * PDIM * NPART + p * NPART + (r0 + rl)];
        }
        __syncthreads();

        // --- edge phase: every thread runs one full edge MLP ---
        {
            float h1[HID];
            int w2o, b2o, w3o, b3o;
            if (t < 236) {                      // fr edges: 4 receivers * 59 senders
                const int rl = t / 59;
                const int i  = t - rl * 59;
                const int r  = r0 + rl;
                const int s  = i + (i >= r ? 1 : 0);
                const float4* av = reinterpret_cast<const float4*>(sm + OFF_A + rl * HID);
                const float4* bv = reinterpret_cast<const float4*>(
                    g_Bv + ((size_t)b * NPART + s) * HID);
#pragma unroll
                for (int k4 = 0; k4 < HID / 4; k4++) {
                    const float4 a4 = av[k4];
                    const float4 b4 = bv[k4];
                    h1[4 * k4 + 0] = fmaxf(a4.x + b4.x, 0.0f);
                    h1[4 * k4 + 1] = fmaxf(a4.y + b4.y, 0.0f);
                    h1[4 * k4 + 2] = fmaxf(a4.z + b4.z, 0.0f);
                    h1[4 * k4 + 3] = fmaxf(a4.w + b4.w, 0.0f);
                }
                w2o = OFF_FRW2; b2o = OFF_FRB2; w3o = OFF_FRW3; b3o = OFF_FRB3;
            } else {                            // pv edges: 4 receivers * 5 vertices
                const int u  = t - 236;
                const int rl = u / NVERT;
                const int v  = u - rl * NVERT;
                const float4* av = reinterpret_cast<const float4*>(sm + OFF_APV + rl * HID);
                const float4* cv = reinterpret_cast<const float4*>(sm + OFF_CV + v * HID);
#pragma unroll
                for (int k4 = 0; k4 < HID / 4; k4++) {
                    const float4 a4 = av[k4];
                    const float4 c4 = cv[k4];
                    h1[4 * k4 + 0] = fmaxf(a4.x + c4.x, 0.0f);
                    h1[4 * k4 + 1] = fmaxf(a4.y + c4.y, 0.0f);
                    h1[4 * k4 + 2] = fmaxf(a4.z + c4.z, 0.0f);
                    h1[4 * k4 + 3] = fmaxf(a4.w + c4.w, 0.0f);
                }
                w2o = OFF_PVW2; b2o = OFF_PVB2; w3o = OFF_PVW3; b3o = OFF_PVB3;
            }

            float e[DE];
            mlp_tail(sm, w2o, b2o, w3o, b3o, h1, e);
#pragma unroll
            for (int j = 0; j < DE; j++)
                sm[OFF_STG + t * 21 + j] = e[j];
        }
        __syncthreads();

        // --- fixed-order reductions into C = [x | Ebar_pp | Ebar_pv] ---
        if (t < 80) {                   // Ebar_pp: sum 59 fr edges
            const int rl = t / DE;
            const int j  = t - rl * DE;
            float acc = 0.0f;
            for (int i = 0; i < 59; i++)
                acc += sm[OFF_STG + (rl * 59 + i) * 21 + j];
            sm[OFF_C + rl * HID + PDIM + j] = acc;
        } else if (t < 160) {           // Ebar_pv: sum 5 pv edges
            const int u  = t - 80;
            const int rl = u / DE;
            const int j  = u - rl * DE;
            float acc = 0.0f;
#pragma unroll
            for (int v = 0; v < NVERT; v++)
                acc += sm[OFF_STG + (236 + rl * NVERT + v) * 21 + j];
            sm[OFF_C + rl * HID + 2 * PDIM + j] = acc;
        }
        __syncthreads();

        // --- fo MLP, layer 1 (4*60 dot products) ---
        if (t < 4 * HID) {
            const int rl = t / HID;
            const int j  = t - rl * HID;
            float acc = sm[OFF_FOB1 + j];
#pragma unroll
            for (int k = 0; k < HID; k++)
                acc = fmaf(sm[OFF_C + rl * HID + k], sm[OFF_FOW1 + k * HID + j], acc);
            sm[OFF_H1S + t] = fmaxf(acc, 0.0f);
        }
        __syncthreads();

        // --- fo layer 2 ---
        if (t < 4 * HID) {
            const int rl = t / HID;
            const int j  = t - rl * HID;
            float acc = sm[OFF_FOB2 + j];
#pragma unroll
            for (int k = 0; k < HID; k++)
                acc = fmaf(sm[OFF_H1S + rl * HID + k], sm[OFF_FOW2 + k * HID + j], acc);
            sm[OFF_H2S + t] = fmaxf(acc, 0.0f);
        }
        __syncthreads();

        // --- fo layer 3 (4*24 outputs) ---
        if (t < 4 * DOUT) {
            const int rl = t / DOUT;
            const int j  = t - rl * DOUT;
            float acc = sm[OFF_FOB3 + j];
#pragma unroll
            for (int k = 0; k < HID; k++)
                acc = fmaf(sm[OFF_H2S + rl * HID + k], sm[OFF_FOW3 + k * DOUT + j], acc);
            sm[OFF_O + rl * DOUT + j] = fmaxf(acc, 0.0f);
        }
        __syncthreads();

        // --- sum O over the 4 receivers, write partial ---
        if (t < DOUT) {
            const float acc = sm[OFF_O + t] + sm[OFF_O + DOUT + t] +
                              sm[OFF_O + 2 * DOUT + t] + sm[OFF_O + 3 * DOUT + t];
            g_Osum[(size_t)tile * DOUT + t] = acc;
        }
        __syncthreads();   // protect staging/C before next tile overwrites
    }
}

// ============================================================
// Kernel 3: per-batch reduce over 15 tiles + fc head
// ============================================================
__global__ void final_kernel(const float* __restrict__ fc_w,
                             const float* __restrict__ fc_b,
                             float* __restrict__ out)
{
    __shared__ float os[DOUT];
    const int b = blockIdx.x;
    const int t = threadIdx.x;
    if (t < DOUT) {
        float acc = 0.0f;
#pragma unroll
        for (int q = 0; q < NQUAD; q++)
            acc += g_Osum[((size_t)b * NQUAD + q) * DOUT + t];
        os[t] = acc;
    }
    __syncthreads();
    if (t < 2) {
        float acc = fc_b[t];
#pragma unroll
        for (int j = 0; j < DOUT; j++)
            acc = fmaf(os[j], fc_w[j * 2 + t], acc);
        out[b * 2 + t] = acc;
    }
}

// ============================================================
extern "C" void kernel_launch(void* const* d_in, const int* in_sizes, int n_in,
                              void* d_out, int out_size)
{
    const float* x     = (const float*)d_in[0];
    const float* y     = (const float*)d_in[1];
    const float* fr_w1 = (const float*)d_in[2];
    const float* fr_b1 = (const float*)d_in[3];
    const float* fr_w2 = (const float*)d_in[4];
    const float* fr_b2 = (const float*)d_in[5];
    const float* fr_w3 = (const float*)d_in[6];
    const float* fr_b3 = (const float*)d_in[7];
    const float* pv_w1 = (const float*)d_in[8];
    const float* pv_b1 = (const float*)d_in[9];
    const float* pv_w2 = (const float*)d_in[10];
    const float* pv_b2 = (const float*)d_in[11];
    const float* pv_w3 = (const float*)d_in[12];
    const float* pv_b3 = (const float*)d_in[13];
    const float* fo_w1 = (const float*)d_in[14];
    const float* fo_b1 = (const float*)d_in[15];
    const float* fo_w2 = (const float*)d_in[16];
    const float* fo_b2 = (const float*)d_in[17];
    const float* fo_w3 = (const float*)d_in[18];
    const float* fo_b3 = (const float*)d_in[19];
    const float* fc_w  = (const float*)d_in[20];
    const float* fc_b  = (const float*)d_in[21];
    float* out = (float*)d_out;

    precompute_kernel<<<BATCH, THREADS>>>(x, y, fr_w1, fr_b1, pv_w1, pv_b1);

    cudaFuncSetAttribute(main_kernel,
                         cudaFuncAttributeMaxDynamicSharedMemorySize, SMEM_BYTES);
    main_kernel<<<148, THREADS, SMEM_BYTES>>>(
        x,
        fr_w2, fr_b2, fr_w3, fr_b3,
        pv_w2, pv_b2, pv_w3, pv_b3,
        fo_w1, fo_b1, fo_w2, fo_b2, fo_w3, fo_b3);

    final_kernel<<<BATCH, 32>>>(fc_w, fc_b, out);
}

// round 5
// speedup vs baseline: 1.0010x; 1.0010x over previous
#include <cuda_runtime.h>

#define BATCH 512
#define NPART 60
#define PDIM 20
#define SDIM 14
#define NVERT 5
#define HID 60
#define DE 20
#define DOUT 24
#define NQUAD 15                 // NPART / 4
#define NTILES (BATCH * NQUAD)   // 7680
#define THREADS 256

// -------- scratch (static device allocation: allowed) --------
__device__ float g_A  [BATCH * NPART * HID];   // fr receiver part + fr_b1
__device__ float g_Bv [BATCH * NPART * HID];   // fr sender part
__device__ float g_Apv[BATCH * NPART * HID];   // pv receiver part + pv_b1
__device__ float g_Cv [BATCH * NVERT * HID];   // pv vertex part
__device__ float g_Osum[NTILES * DOUT];        // per-tile O partial sums

// -------- shared memory layout (float offsets) --------
#define OFF_FRW2 0
#define OFF_FRW3 3600
#define OFF_PVW2 4800
#define OFF_PVW3 8400
#define OFF_FOW1 9600
#define OFF_FOW2 13200
#define OFF_FOW3 16800
#define OFF_FRB2 18240
#define OFF_FRB3 18300
#define OFF_PVB2 18320
#define OFF_PVB3 18380
#define OFF_FOB1 18400
#define OFF_FOB2 18460
#define OFF_FOB3 18520
#define OFF_A    18544   // 4*60
#define OFF_APV  18784   // 4*60
#define OFF_CV   19024   // 5*60
#define OFF_C    19324   // 4*60 : [x(20) | Ebar_pp(20) | Ebar_pv(20)] per receiver
#define OFF_H1S  19564   // 4*60
#define OFF_H2S  19804   // 4*60
#define OFF_O    20044   // 4*24 (pad to 96)
#define OFF_STG  20140   // 256*21 staging (stride 21 -> conflict-free)
#define SMEM_FLOATS (OFF_STG + 256 * 21)
#define SMEM_BYTES  (SMEM_FLOATS * 4)

// ============================================================
// Kernel 1: per-particle / per-vertex first-layer precompute
// ============================================================
__global__ void precompute_kernel(const float* __restrict__ x,
                                  const float* __restrict__ y,
                                  const float* __restrict__ fr_w1,
                                  const float* __restrict__ fr_b1,
                                  const float* __restrict__ pv_w1,
                                  const float* __restrict__ pv_b1)
{
    __shared__ float xb[PDIM * NPART];   // x[b] slice, layout [p][n]
    __shared__ float yb[SDIM * NVERT];   // y[b] slice, layout [s][v]
    const int b   = blockIdx.x;
    const int tid = threadIdx.x;

    for (int i = tid; i < PDIM * NPART; i += blockDim.x)
        xb[i] = x[(size_t)b * PDIM * NPART + i];
    for (int i = tid; i < SDIM * NVERT; i += blockDim.x)
        yb[i] = y[(size_t)b * SDIM * NVERT + i];
    __syncthreads();

    for (int idx = tid; idx < NPART * HID; idx += blockDim.x) {
        const int n = idx / HID;
        const int h = idx - n * HID;
        float a1 = fr_b1[h];
        float a2 = 0.0f;
        float a3 = pv_b1[h];
#pragma unroll
        for (int p = 0; p < PDIM; p++) {
            const float xv = xb[p * NPART + n];     // xt[b][n][p]
            a1 = fmaf(xv, fr_w1[p * HID + h], a1);
            a2 = fmaf(xv, fr_w1[(PDIM + p) * HID + h], a2);
            a3 = fmaf(xv, pv_w1[p * HID + h], a3);
        }
        const size_t o = (size_t)b * NPART * HID + idx;
        g_A[o]   = a1;
        g_Bv[o]  = a2;
        g_Apv[o] = a3;
    }

    for (int idx = tid; idx < NVERT * HID; idx += blockDim.x) {
        const int v = idx / HID;
        const int h = idx - v * HID;
        float a = 0.0f;
#pragma unroll
        for (int s = 0; s < SDIM; s++)
            a = fmaf(yb[s * NVERT + v], pv_w1[(PDIM + s) * HID + h], a);
        g_Cv[(size_t)b * NVERT * HID + idx] = a;
    }
}

// ============================================================
// MLP layers 2..3 (60->60->20, relu each), weights in SMEM
// ============================================================
__device__ __forceinline__ void mlp_tail(const float* __restrict__ sm,
                                         int w2o, int b2o, int w3o, int b3o,
                                         const float h1[HID], float e[DE])
{
    float h2[HID];
#pragma unroll
    for (int j = 0; j < HID; j++) h2[j] = sm[b2o + j];
#pragma unroll
    for (int k = 0; k < HID; k++) {
        const float a = h1[k];
        const float4* wr = reinterpret_cast<const float4*>(sm + w2o + k * HID);
#pragma unroll
        for (int j4 = 0; j4 < HID / 4; j4++) {
            const float4 w = wr[j4];
            h2[4 * j4 + 0] = fmaf(a, w.x, h2[4 * j4 + 0]);
            h2[4 * j4 + 1] = fmaf(a, w.y, h2[4 * j4 + 1]);
            h2[4 * j4 + 2] = fmaf(a, w.z, h2[4 * j4 + 2]);
            h2[4 * j4 + 3] = fmaf(a, w.w, h2[4 * j4 + 3]);
        }
    }
#pragma unroll
    for (int j = 0; j < HID; j++) h2[j] = fmaxf(h2[j], 0.0f);

#pragma unroll
    for (int j = 0; j < DE; j++) e[j] = sm[b3o + j];
#pragma unroll
    for (int k = 0; k < HID; k++) {
        const float a = h2[k];
        const float4* wr = reinterpret_cast<const float4*>(sm + w3o + k * DE);
#pragma unroll
        for (int j4 = 0; j4 < DE / 4; j4++) {
            const float4 w = wr[j4];
            e[4 * j4 + 0] = fmaf(a, w.x, e[4 * j4 + 0]);
            e[4 * j4 + 1] = fmaf(a, w.y, e[4 * j4 + 1]);
            e[4 * j4 + 2] = fmaf(a, w.z, e[4 * j4 + 2]);
            e[4 * j4 + 3] = fmaf(a, w.w, e[4 * j4 + 3]);
        }
    }
#pragma unroll
    for (int j = 0; j < DE; j++) e[j] = fmaxf(e[j], 0.0f);
}

__device__ __forceinline__ void smem_copy(float* dst, const float* __restrict__ src,
                                          int n, int tid)
{
    for (int i = tid; i < n; i += THREADS) dst[i] = src[i];
}

// ============================================================
// Kernel 2: persistent main kernel. Tile = (batch, 4 receivers)
// ============================================================
__global__ void __launch_bounds__(THREADS, 1)
main_kernel(const float* __restrict__ x,
            const float* __restrict__ fr_w2, const float* __restrict__ fr_b2,
            const float* __restrict__ fr_w3, const float* __restrict__ fr_b3,
            const float* __restrict__ pv_w2, const float* __restrict__ pv_b2,
            const float* __restrict__ pv_w3, const float* __restrict__ pv_b3,
            const float* __restrict__ fo_w1, const float* __restrict__ fo_b1,
            const float* __restrict__ fo_w2, const float* __restrict__ fo_b2,
            const float* __restrict__ fo_w3, const float* __restrict__ fo_b3)
{
    extern __shared__ float sm[];
    const int t = threadIdx.x;

    // --- load all weights once per block ---
    smem_copy(sm + OFF_FRW2, fr_w2, HID * HID, t);
    smem_copy(sm + OFF_FRW3, fr_w3, HID * DE, t);
    smem_copy(sm + OFF_PVW2, pv_w2, HID * HID, t);
    smem_copy(sm + OFF_PVW3, pv_w3, HID * DE, t);
    smem_copy(sm + OFF_FOW1, fo_w1, HID * HID, t);
    smem_copy(sm + OFF_FOW2, fo_w2, HID * HID, t);
    smem_copy(sm + OFF_FOW3, fo_w3, HID * DOUT, t);
    smem_copy(sm + OFF_FRB2, fr_b2, HID, t);
    smem_copy(sm + OFF_FRB3, fr_b3, DE, t);
    smem_copy(sm + OFF_PVB2, pv_b2, HID, t);
    smem_copy(sm + OFF_PVB3, pv_b3, DE, t);
    smem_copy(sm + OFF_FOB1, fo_b1, HID, t);
    smem_copy(sm + OFF_FOB2, fo_b2, HID, t);
    smem_copy(sm + OFF_FOB3, fo_b3, DOUT, t);
    __syncthreads();

    for (int tile = blockIdx.x; tile < NTILES; tile += gridDim.x) {
        const int b  = tile / NQUAD;
        const int q  = tile - b * NQUAD;
        const int r0 = q * 4;

        // --- stage per-tile inputs ---
        for (int i = t; i < 4 * HID; i += THREADS)
            sm[OFF_A + i] = g_A[((size_t)b * NPART + r0) * HID + i];
        for (int i = t; i < 4 * HID; i += THREADS)
            sm[OFF_APV + i] = g_Apv[((size_t)b * NPART + r0) * HID + i];
        for (int i = t; i < NVERT * HID; i += THREADS)
            sm[OFF_CV + i] = g_Cv[(size_t)b * NVERT * HID + i];
        // xt slice for the 4 receivers: sC[rl][p] = x[b, p, r0+rl]
        for (int i = t; i < 4 * PDIM; i += THREADS) {
            const int rl = i / PDIM;
            const int p  = i - rl * PDIM;
            sm[OFF_C + rl * HID + p] =
                x[(size_t)b * PDIM * NPART + p * NPART + (r0 + rl)];
        }
        __syncthreads();

        // --- edge phase: every thread runs one full edge MLP ---
        {
            float h1[HID];
            int w2o, b2o, w3o, b3o;
            if (t < 236) {                      // fr edges: 4 receivers * 59 senders
                const int rl = t / 59;
                const int i  = t - rl * 59;
                const int r  = r0 + rl;
                const int s  = i + (i >= r ? 1 : 0);
                const float4* av = reinterpret_cast<const float4*>(sm + OFF_A + rl * HID);
                const float4* bv = reinterpret_cast<const float4*>(
                    g_Bv + ((size_t)b * NPART + s) * HID);
#pragma unroll
                for (int k4 = 0; k4 < HID / 4; k4++) {
                    const float4 a4 = av[k4];
                    const float4 b4 = bv[k4];
                    h1[4 * k4 + 0] = fmaxf(a4.x + b4.x, 0.0f);
                    h1[4 * k4 + 1] = fmaxf(a4.y + b4.y, 0.0f);
                    h1[4 * k4 + 2] = fmaxf(a4.z + b4.z, 0.0f);
                    h1[4 * k4 + 3] = fmaxf(a4.w + b4.w, 0.0f);
                }
                w2o = OFF_FRW2; b2o = OFF_FRB2; w3o = OFF_FRW3; b3o = OFF_FRB3;
            } else {                            // pv edges: 4 receivers * 5 vertices
                const int u  = t - 236;
                const int rl = u / NVERT;
                const int v  = u - rl * NVERT;
                const float4* av = reinterpret_cast<const float4*>(sm + OFF_APV + rl * HID);
                const float4* cv = reinterpret_cast<const float4*>(sm + OFF_CV + v * HID);
#pragma unroll
                for (int k4 = 0; k4 < HID / 4; k4++) {
                    const float4 a4 = av[k4];
                    const float4 c4 = cv[k4];
                    h1[4 * k4 + 0] = fmaxf(a4.x + c4.x, 0.0f);
                    h1[4 * k4 + 1] = fmaxf(a4.y + c4.y, 0.0f);
                    h1[4 * k4 + 2] = fmaxf(a4.z + c4.z, 0.0f);
                    h1[4 * k4 + 3] = fmaxf(a4.w + c4.w, 0.0f);
                }
                w2o = OFF_PVW2; b2o = OFF_PVB2; w3o = OFF_PVW3; b3o = OFF_PVB3;
            }

            float e[DE];
            mlp_tail(sm, w2o, b2o, w3o, b3o, h1, e);
#pragma unroll
            for (int j = 0; j < DE; j++)
                sm[OFF_STG + t * 21 + j] = e[j];
        }
        __syncthreads();

        // --- fixed-order reductions into C = [x | Ebar_pp | Ebar_pv] ---
        if (t < 80) {                   // Ebar_pp: sum 59 fr edges
            const int rl = t / DE;
            const int j  = t - rl * DE;
            float acc = 0.0f;
            for (int i = 0; i < 59; i++)
                acc += sm[OFF_STG + (rl * 59 + i) * 21 + j];
            sm[OFF_C + rl * HID + PDIM + j] = acc;
        } else if (t < 160) {           // Ebar_pv: sum 5 pv edges
            const int u  = t - 80;
            const int rl = u / DE;
            const int j  = u - rl * DE;
            float acc = 0.0f;
#pragma unroll
            for (int v = 0; v < NVERT; v++)
                acc += sm[OFF_STG + (236 + rl * NVERT + v) * 21 + j];
            sm[OFF_C + rl * HID + 2 * PDIM + j] = acc;
        }
        __syncthreads();

        // --- fo MLP, layer 1 (4*60 dot products) ---
        if (t < 4 * HID) {
            const int rl = t / HID;
            const int j  = t - rl * HID;
            float acc = sm[OFF_FOB1 + j];
#pragma unroll
            for (int k = 0; k < HID; k++)
                acc = fmaf(sm[OFF_C + rl * HID + k], sm[OFF_FOW1 + k * HID + j], acc);
            sm[OFF_H1S + t] = fmaxf(acc, 0.0f);
        }
        __syncthreads();

        // --- fo layer 2 ---
        if (t < 4 * HID) {
            const int rl = t / HID;
            const int j  = t - rl * HID;
            float acc = sm[OFF_FOB2 + j];
#pragma unroll
            for (int k = 0; k < HID; k++)
                acc = fmaf(sm[OFF_H1S + rl * HID + k], sm[OFF_FOW2 + k * HID + j], acc);
            sm[OFF_H2S + t] = fmaxf(acc, 0.0f);
        }
        __syncthreads();

        // --- fo layer 3 (4*24 outputs) ---
        if (t < 4 * DOUT) {
            const int rl = t / DOUT;
            const int j  = t - rl * DOUT;
            float acc = sm[OFF_FOB3 + j];
#pragma unroll
            for (int k = 0; k < HID; k++)
                acc = fmaf(sm[OFF_H2S + rl * HID + k], sm[OFF_FOW3 + k * DOUT + j], acc);
            sm[OFF_O + rl * DOUT + j] = fmaxf(acc, 0.0f);
        }
        __syncthreads();

        // --- sum O over the 4 receivers, write partial ---
        if (t < DOUT) {
            const float acc = sm[OFF_O + t] + sm[OFF_O + DOUT + t] +
                              sm[OFF_O + 2 * DOUT + t] + sm[OFF_O + 3 * DOUT + t];
            g_Osum[(size_t)tile * DOUT + t] = acc;
        }
        __syncthreads();   // protect staging/C before next tile overwrites
    }
}

// ============================================================
// Kernel 3: per-batch reduce over 15 tiles + fc head
// ============================================================
__global__ void final_kernel(const float* __restrict__ fc_w,
                             const float* __restrict__ fc_b,
                             float* __restrict__ out)
{
    __shared__ float os[DOUT];
    const int b = blockIdx.x;
    const int t = threadIdx.x;
    if (t < DOUT) {
        float acc = 0.0f;
#pragma unroll
        for (int q = 0; q < NQUAD; q++)
            acc += g_Osum[((size_t)b * NQUAD + q) * DOUT + t];
        os[t] = acc;
    }
    __syncthreads();
    if (t < 2) {
        float acc = fc_b[t];
#pragma unroll
        for (int j = 0; j < DOUT; j++)
            acc = fmaf(os[j], fc_w[j * 2 + t], acc);
        out[b * 2 + t] = acc;
    }
}

// ============================================================
extern "C" void kernel_launch(void* const* d_in, const int* in_sizes, int n_in,
                              void* d_out, int out_size)
{
    const float* x     = (const float*)d_in[0];
    const float* y     = (const float*)d_in[1];
    const float* fr_w1 = (const float*)d_in[2];
    const float* fr_b1 = (const float*)d_in[3];
    const float* fr_w2 = (const float*)d_in[4];
    const float* fr_b2 = (const float*)d_in[5];
    const float* fr_w3 = (const float*)d_in[6];
    const float* fr_b3 = (const float*)d_in[7];
    const float* pv_w1 = (const float*)d_in[8];
    const float* pv_b1 = (const float*)d_in[9];
    const float* pv_w2 = (const float*)d_in[10];
    const float* pv_b2 = (const float*)d_in[11];
    const float* pv_w3 = (const float*)d_in[12];
    const float* pv_b3 = (const float*)d_in[13];
    const float* fo_w1 = (const float*)d_in[14];
    const float* fo_b1 = (const float*)d_in[15];
    const float* fo_w2 = (const float*)d_in[16];
    const float* fo_b2 = (const float*)d_in[17];
    const float* fo_w3 = (const float*)d_in[18];
    const float* fo_b3 = (const float*)d_in[19];
    const float* fc_w  = (const float*)d_in[20];
    const float* fc_b  = (const float*)d_in[21];
    float* out = (float*)d_out;

    precompute_kernel<<<BATCH, THREADS>>>(x, y, fr_w1, fr_b1, pv_w1, pv_b1);

    cudaFuncSetAttribute(main_kernel,
                         cudaFuncAttributeMaxDynamicSharedMemorySize, SMEM_BYTES);
    main_kernel<<<148, THREADS, SMEM_BYTES>>>(
        x,
        fr_w2, fr_b2, fr_w3, fr_b3,
        pv_w2, pv_b2, pv_w3, pv_b3,
        fo_w1, fo_b1, fo_w2, fo_b2, fo_w3, fo_b3);

    final_kernel<<<BATCH, 32>>>(fc_w, fc_b, out);
}

// round 8
// speedup vs baseline: 1.0201x; 1.0191x over previous
#include <cuda_runtime.h>

#define BATCH 512
#define NPART 60
#define PDIM 20
#define SDIM 14
#define NVERT 5
#define HID 60
#define DE 20
#define DOUT 24
#define NQUAD 15                 // NPART / 4
#define NTILES (BATCH * NQUAD)   // 7680
#define THREADS 256

// -------- scratch (static device allocation: allowed) --------
__device__ float g_A  [BATCH * NPART * HID];   // fr receiver part + fr_b1
__device__ float g_Bv [BATCH * NPART * HID];   // fr sender part
__device__ float g_Apv[BATCH * NPART * HID];   // pv receiver part + pv_b1
__device__ float g_Cv [BATCH * NVERT * HID];   // pv vertex part
__device__ float g_Osum[NTILES * DOUT];        // per-tile O partial sums

// -------- shared memory layout (float offsets, all 16B aligned) --------
#define OFF_FRW2 0
#define OFF_FRW3 3600
#define OFF_PVW2 4800
#define OFF_PVW3 8400
#define OFF_FOW1 9600
#define OFF_FOW2 13200
#define OFF_FOW3 16800
#define OFF_FRB2 18240
#define OFF_FRB3 18300
#define OFF_PVB2 18320
#define OFF_PVB3 18380
#define OFF_FOB1 18400
#define OFF_FOB2 18460
#define OFF_FOB3 18520
#define OFF_A    18544   // 4*60
#define OFF_APV  18784   // 4*60
#define OFF_CV   19024   // 5*60
#define OFF_C    19324   // 4*60 : [x(20) | Ebar_pp(20) | Ebar_pv(20)] per receiver
#define OFF_H1S  19564   // 4*60
#define OFF_H2S  19804   // 4*60
#define OFF_O    20044   // 4*24 (pad to 96)
#define OFF_STG  20140   // 256*21 staging (stride 21 -> conflict-free)
#define SMEM_FLOATS (OFF_STG + 256 * 21)
#define SMEM_BYTES  (SMEM_FLOATS * 4)

// -------- packed fp32x2 helpers (Blackwell f32x2 pipe; ptxas won't auto-fuse) --------
typedef unsigned long long u64t;

__device__ __forceinline__ u64t pack2(float a, float b) {
    u64t r; asm("mov.b64 %0, {%1, %2};" : "=l"(r) : "f"(a), "f"(b)); return r;
}
__device__ __forceinline__ void unpack2(u64t v, float& a, float& b) {
    asm("mov.b64 {%0, %1}, %2;" : "=f"(a), "=f"(b) : "l"(v));
}
__device__ __forceinline__ u64t fma2(u64t a, u64t b, u64t c) {
    u64t d; asm("fma.rn.f32x2 %0, %1, %2, %3;" : "=l"(d) : "l"(a), "l"(b), "l"(c));
    return d;
}

// ============================================================
// Kernel 1: per-particle / per-vertex first-layer precompute
// (weights staged in SMEM to kill the gmem latency chain)
// ============================================================
__global__ void precompute_kernel(const float* __restrict__ x,
                                  const float* __restrict__ y,
                                  const float* __restrict__ fr_w1,
                                  const float* __restrict__ fr_b1,
                                  const float* __restrict__ pv_w1,
                                  const float* __restrict__ pv_b1)
{
    __shared__ float xb[PDIM * NPART];                 // x[b] slice [p][n]
    __shared__ float yb[SDIM * NVERT];                 // y[b] slice [s][v]
    __shared__ float s_frw[2 * PDIM * HID];            // fr_w1 (40x60)
    __shared__ float s_pvw[(PDIM + SDIM) * HID];       // pv_w1 (34x60)
    __shared__ float s_frb[HID], s_pvb[HID];
    const int b   = blockIdx.x;
    const int tid = threadIdx.x;

    for (int i = tid; i < PDIM * NPART; i += blockDim.x)
        xb[i] = x[(size_t)b * PDIM * NPART + i];
    for (int i = tid; i < SDIM * NVERT; i += blockDim.x)
        yb[i] = y[(size_t)b * SDIM * NVERT + i];
    for (int i = tid; i < 2 * PDIM * HID; i += blockDim.x)
        s_frw[i] = fr_w1[i];
    for (int i = tid; i < (PDIM + SDIM) * HID; i += blockDim.x)
        s_pvw[i] = pv_w1[i];
    for (int i = tid; i < HID; i += blockDim.x) {
        s_frb[i] = fr_b1[i];
        s_pvb[i] = pv_b1[i];
    }
    __syncthreads();

    for (int idx = tid; idx < NPART * HID; idx += blockDim.x) {
        const int n = idx / HID;
        const int h = idx - n * HID;
        float a1 = s_frb[h];
        float a2 = 0.0f;
        float a3 = s_pvb[h];
#pragma unroll
        for (int p = 0; p < PDIM; p++) {
            const float xv = xb[p * NPART + n];     // xt[b][n][p]
            a1 = fmaf(xv, s_frw[p * HID + h], a1);
            a2 = fmaf(xv, s_frw[(PDIM + p) * HID + h], a2);
            a3 = fmaf(xv, s_pvw[p * HID + h], a3);
        }
        const size_t o = (size_t)b * NPART * HID + idx;
        g_A[o]   = a1;
        g_Bv[o]  = a2;
        g_Apv[o] = a3;
    }

    for (int idx = tid; idx < NVERT * HID; idx += blockDim.x) {
        const int v = idx / HID;
        const int h = idx - v * HID;
        float a = 0.0f;
#pragma unroll
        for (int s = 0; s < SDIM; s++)
            a = fmaf(yb[s * NVERT + v], s_pvw[(PDIM + s) * HID + h], a);
        g_Cv[(size_t)b * NVERT * HID + idx] = a;
    }
}

// ============================================================
// MLP layers 2..3 (60->60->20, relu each) with packed f32x2 FMA.
// hs[] holds h1 on entry, gets overwritten by relu(h2).
// ============================================================
__device__ __forceinline__ void mlp_tail2(const float* __restrict__ sm,
                                          int w2o, int b2o, int w3o, int b3o,
                                          float hs[HID], float e[DE])
{
    u64t h2[HID / 2];
    {
        const ulonglong2* bv = reinterpret_cast<const ulonglong2*>(sm + b2o);
#pragma unroll
        for (int j = 0; j < HID / 4; j++) {
            const ulonglong2 v = bv[j];
            h2[2 * j]     = v.x;
            h2[2 * j + 1] = v.y;
        }
    }
#pragma unroll
    for (int k = 0; k < HID; k++) {
        const u64t ap = pack2(hs[k], hs[k]);
        const ulonglong2* wr = reinterpret_cast<const ulonglong2*>(sm + w2o + k * HID);
#pragma unroll
        for (int j = 0; j < HID / 4; j++) {
            const ulonglong2 w = wr[j];                 // one LDS.128 = 4 weights
            h2[2 * j]     = fma2(w.x, ap, h2[2 * j]);
            h2[2 * j + 1] = fma2(w.y, ap, h2[2 * j + 1]);
        }
    }
#pragma unroll
    for (int j = 0; j < HID / 2; j++) {
        float a, b;
        unpack2(h2[j], a, b);
        hs[2 * j]     = fmaxf(a, 0.0f);
        hs[2 * j + 1] = fmaxf(b, 0.0f);
    }

    u64t e2[DE / 2];
    {
        const ulonglong2* bv = reinterpret_cast<const ulonglong2*>(sm + b3o);
#pragma unroll
        for (int j = 0; j < DE / 4; j++) {
            const ulonglong2 v = bv[j];
            e2[2 * j]     = v.x;
            e2[2 * j + 1] = v.y;
        }
    }
#pragma unroll
    for (int k = 0; k < HID; k++) {
        const u64t ap = pack2(hs[k], hs[k]);
        const ulonglong2* wr = reinterpret_cast<const ulonglong2*>(sm + w3o + k * DE);
#pragma unroll
        for (int j = 0; j < DE / 4; j++) {
            const ulonglong2 w = wr[j];
            e2[2 * j]     = fma2(w.x, ap, e2[2 * j]);
            e2[2 * j + 1] = fma2(w.y, ap, e2[2 * j + 1]);
        }
    }
#pragma unroll
    for (int j = 0; j < DE / 2; j++) {
        float a, b;
        unpack2(e2[j], a, b);
        e[2 * j]     = fmaxf(a, 0.0f);
        e[2 * j + 1] = fmaxf(b, 0.0f);
    }
}

__device__ __forceinline__ void smem_copy(float* dst, const float* __restrict__ src,
                                          int n, int tid)
{
    for (int i = tid; i < n; i += THREADS) dst[i] = src[i];
}

// ============================================================
// Kernel 2: persistent main kernel. Tile = (batch, 4 receivers)
// ============================================================
__global__ void __launch_bounds__(THREADS, 1)
main_kernel(const float* __restrict__ x,
            const float* __restrict__ fr_w2, const float* __restrict__ fr_b2,
            const float* __restrict__ fr_w3, const float* __restrict__ fr_b3,
            const float* __restrict__ pv_w2, const float* __restrict__ pv_b2,
            const float* __restrict__ pv_w3, const float* __restrict__ pv_b3,
            const float* __restrict__ fo_w1, const float* __restrict__ fo_b1,
            const float* __restrict__ fo_w2, const float* __restrict__ fo_b2,
            const float* __restrict__ fo_w3, const float* __restrict__ fo_b3)
{
    extern __shared__ float sm[];
    const int t = threadIdx.x;

    // --- load all weights once per block ---
    smem_copy(sm + OFF_FRW2, fr_w2, HID * HID, t);
    smem_copy(sm + OFF_FRW3, fr_w3, HID * DE, t);
    smem_copy(sm + OFF_PVW2, pv_w2, HID * HID, t);
    smem_copy(sm + OFF_PVW3, pv_w3, HID * DE, t);
    smem_copy(sm + OFF_FOW1, fo_w1, HID * HID, t);
    smem_copy(sm + OFF_FOW2, fo_w2, HID * HID, t);
    smem_copy(sm + OFF_FOW3, fo_w3, HID * DOUT, t);
    smem_copy(sm + OFF_FRB2, fr_b2, HID, t);
    smem_copy(sm + OFF_FRB3, fr_b3, DE, t);
    smem_copy(sm + OFF_PVB2, pv_b2, HID, t);
    smem_copy(sm + OFF_PVB3, pv_b3, DE, t);
    smem_copy(sm + OFF_FOB1, fo_b1, HID, t);
    smem_copy(sm + OFF_FOB2, fo_b2, HID, t);
    smem_copy(sm + OFF_FOB3, fo_b3, DOUT, t);
    __syncthreads();

    for (int tile = blockIdx.x; tile < NTILES; tile += gridDim.x) {
        const int b  = tile / NQUAD;
        const int q  = tile - b * NQUAD;
        const int r0 = q * 4;

        // --- stage per-tile inputs ---
        for (int i = t; i < 4 * HID; i += THREADS)
            sm[OFF_A + i] = g_A[((size_t)b * NPART + r0) * HID + i];
        for (int i = t; i < 4 * HID; i += THREADS)
            sm[OFF_APV + i] = g_Apv[((size_t)b * NPART + r0) * HID + i];
        for (int i = t; i < NVERT * HID; i += THREADS)
            sm[OFF_CV + i] = g_Cv[(size_t)b * NVERT * HID + i];
        // xt slice for the 4 receivers: sC[rl][p] = x[b, p, r0+rl]
        for (int i = t; i < 4 * PDIM; i += THREADS) {
            const int rl = i / PDIM;
            const int p  = i - rl * PDIM;
            sm[OFF_C + rl * HID + p] =
                x[(size_t)b * PDIM * NPART + p * NPART + (r0 + rl)];
        }
        __syncthreads();

        // --- edge phase: every thread runs one full edge MLP ---
        {
            float hs[HID];
            int w2o, b2o, w3o, b3o;
            if (t < 236) {                      // fr edges: 4 receivers * 59 senders
                const int rl = t / 59;
                const int i  = t - rl * 59;
                const int r  = r0 + rl;
                const int s  = i + (i >= r ? 1 : 0);
                const float4* av = reinterpret_cast<const float4*>(sm + OFF_A + rl * HID);
                const float4* bv = reinterpret_cast<const float4*>(
                    g_Bv + ((size_t)b * NPART + s) * HID);
#pragma unroll
                for (int k4 = 0; k4 < HID / 4; k4++) {
                    const float4 a4 = av[k4];
                    const float4 b4 = bv[k4];
                    hs[4 * k4 + 0] = fmaxf(a4.x + b4.x, 0.0f);
                    hs[4 * k4 + 1] = fmaxf(a4.y + b4.y, 0.0f);
                    hs[4 * k4 + 2] = fmaxf(a4.z + b4.z, 0.0f);
                    hs[4 * k4 + 3] = fmaxf(a4.w + b4.w, 0.0f);
                }
                w2o = OFF_FRW2; b2o = OFF_FRB2; w3o = OFF_FRW3; b3o = OFF_FRB3;
            } else {                            // pv edges: 4 receivers * 5 vertices
                const int u  = t - 236;
                const int rl = u / NVERT;
                const int v  = u - rl * NVERT;
                const float4* av = reinterpret_cast<const float4*>(sm + OFF_APV + rl * HID);
                const float4* cv = reinterpret_cast<const float4*>(sm + OFF_CV + v * HID);
#pragma unroll
                for (int k4 = 0; k4 < HID / 4; k4++) {
                    const float4 a4 = av[k4];
                    const float4 c4 = cv[k4];
                    hs[4 * k4 + 0] = fmaxf(a4.x + c4.x, 0.0f);
                    hs[4 * k4 + 1] = fmaxf(a4.y + c4.y, 0.0f);
                    hs[4 * k4 + 2] = fmaxf(a4.z + c4.z, 0.0f);
                    hs[4 * k4 + 3] = fmaxf(a4.w + c4.w, 0.0f);
                }
                w2o = OFF_PVW2; b2o = OFF_PVB2; w3o = OFF_PVW3; b3o = OFF_PVB3;
            }

            float e[DE];
            mlp_tail2(sm, w2o, b2o, w3o, b3o, hs, e);
#pragma unroll
            for (int j = 0; j < DE; j++)
                sm[OFF_STG + t * 21 + j] = e[j];
        }
        __syncthreads();

        // --- fixed-order reductions into C = [x | Ebar_pp | Ebar_pv] ---
        if (t < 80) {                   // Ebar_pp: sum 59 fr edges
            const int rl = t / DE;
            const int j  = t - rl * DE;
            float acc = 0.0f;
            for (int i = 0; i < 59; i++)
                acc += sm[OFF_STG + (rl * 59 + i) * 21 + j];
            sm[OFF_C + rl * HID + PDIM + j] = acc;
        } else if (t < 160) {           // Ebar_pv: sum 5 pv edges
            const int u  = t - 80;
            const int rl = u / DE;
            const int j  = u - rl * DE;
            float acc = 0.0f;
#pragma unroll
            for (int v = 0; v < NVERT; v++)
                acc += sm[OFF_STG + (236 + rl * NVERT + v) * 21 + j];
            sm[OFF_C + rl * HID + 2 * PDIM + j] = acc;
        }
        __syncthreads();

        // --- fo MLP, layer 1 (4*60 dot products) ---
        if (t < 4 * HID) {
            const int rl = t / HID;
            const int j  = t - rl * HID;
            float acc = sm[OFF_FOB1 + j];
#pragma unroll
            for (int k = 0; k < HID; k++)
                acc = fmaf(sm[OFF_C + rl * HID + k], sm[OFF_FOW1 + k * HID + j], acc);
            sm[OFF_H1S + t] = fmaxf(acc, 0.0f);
        }
        __syncthreads();

        // --- fo layer 2 ---
        if (t < 4 * HID) {
            const int rl = t / HID;
            const int j  = t - rl * HID;
            float acc = sm[OFF_FOB2 + j];
#pragma unroll
            for (int k = 0; k < HID; k++)
                acc = fmaf(sm[OFF_H1S + rl * HID + k], sm[OFF_FOW2 + k * HID + j], acc);
            sm[OFF_H2S + t] = fmaxf(acc, 0.0f);
        }
        __syncthreads();

        // --- fo layer 3 (4*24 outputs) ---
        if (t < 4 * DOUT) {
            const int rl = t / DOUT;
            const int j  = t - rl * DOUT;
            float acc = sm[OFF_FOB3 + j];
#pragma unroll
            for (int k = 0; k < HID; k++)
                acc = fmaf(sm[OFF_H2S + rl * HID + k], sm[OFF_FOW3 + k * DOUT + j], acc);
            sm[OFF_O + rl * DOUT + j] = fmaxf(acc, 0.0f);
        }
        __syncthreads();

        // --- sum O over the 4 receivers, write partial ---
        if (t < DOUT) {
            const float acc = sm[OFF_O + t] + sm[OFF_O + DOUT + t] +
                              sm[OFF_O + 2 * DOUT + t] + sm[OFF_O + 3 * DOUT + t];
            g_Osum[(size_t)tile * DOUT + t] = acc;
        }
        __syncthreads();   // protect staging/C before next tile overwrites
    }
}

// ============================================================
// Kernel 3: per-batch reduce over 15 tiles + fc head
// ============================================================
__global__ void final_kernel(const float* __restrict__ fc_w,
                             const float* __restrict__ fc_b,
                             float* __restrict__ out)
{
    __shared__ float os[DOUT];
    const int b = blockIdx.x;
    const int t = threadIdx.x;
    if (t < DOUT) {
        float acc = 0.0f;
#pragma unroll
        for (int q = 0; q < NQUAD; q++)
            acc += g_Osum[((size_t)b * NQUAD + q) * DOUT + t];
        os[t] = acc;
    }
    __syncthreads();
    if (t < 2) {
        float acc = fc_b[t];
#pragma unroll
        for (int j = 0; j < DOUT; j++)
            acc = fmaf(os[j], fc_w[j * 2 + t], acc);
        out[b * 2 + t] = acc;
    }
}

// ============================================================
extern "C" void kernel_launch(void* const* d_in, const int* in_sizes, int n_in,
                              void* d_out, int out_size)
{
    const float* x     = (const float*)d_in[0];
    const float* y     = (const float*)d_in[1];
    const float* fr_w1 = (const float*)d_in[2];
    const float* fr_b1 = (const float*)d_in[3];
    const float* fr_w2 = (const float*)d_in[4];
    const float* fr_b2 = (const float*)d_in[5];
    const float* fr_w3 = (const float*)d_in[6];
    const float* fr_b3 = (const float*)d_in[7];
    const float* pv_w1 = (const float*)d_in[8];
    const float* pv_b1 = (const float*)d_in[9];
    const float* pv_w2 = (const float*)d_in[10];
    const float* pv_b2 = (const float*)d_in[11];
    const float* pv_w3 = (const float*)d_in[12];
    const float* pv_b3 = (const float*)d_in[13];
    const float* fo_w1 = (const float*)d_in[14];
    const float* fo_b1 = (const float*)d_in[15];
    const float* fo_w2 = (const float*)d_in[16];
    const float* fo_b2 = (const float*)d_in[17];
    const float* fo_w3 = (const float*)d_in[18];
    const float* fo_b3 = (const float*)d_in[19];
    const float* fc_w  = (const float*)d_in[20];
    const float* fc_b  = (const float*)d_in[21];
    float* out = (float*)d_out;

    precompute_kernel<<<BATCH, THREADS>>>(x, y, fr_w1, fr_b1, pv_w1, pv_b1);

    cudaFuncSetAttribute(main_kernel,
                         cudaFuncAttributeMaxDynamicSharedMemorySize, SMEM_BYTES);
    main_kernel<<<148, THREADS, SMEM_BYTES>>>(
        x,
        fr_w2, fr_b2, fr_w3, fr_b3,
        pv_w2, pv_b2, pv_w3, pv_b3,
        fo_w1, fo_b1, fo_w2, fo_b2, fo_w3, fo_b3);

    final_kernel<<<BATCH, 32>>>(fc_w, fc_b, out);
}

// round 12
// speedup vs baseline: 1.0838x; 1.0625x over previous
#include <cuda_runtime.h>

#define BATCH 512
#define NPART 60
#define PDIM 20
#define SDIM 14
#define NVERT 5
#define HID 60
#define DE 20
#define DOUT 24
#define NQUAD 15                 // NPART / 4
#define NTILES (BATCH * NQUAD)   // 7680
#define THREADS 256
#define GRID_MAIN 296            // 2 CTAs per SM

// -------- scratch (static device allocation: allowed) --------
__device__ float g_A  [BATCH * NPART * HID];   // fr receiver part + fr_b1
__device__ float g_Bv [BATCH * NPART * HID];   // fr sender part
__device__ float g_Apv[BATCH * NPART * HID];   // pv receiver part + pv_b1
__device__ float g_Cv [BATCH * NVERT * HID];   // pv vertex part
__device__ float g_Osum[NTILES * DOUT];        // per-tile O partial sums

// -------- shared memory layout (float offsets, all 16B aligned) --------
#define OFF_FRW2 0
#define OFF_FRW3 3600
#define OFF_PVW2 4800
#define OFF_PVW3 8400
#define OFF_FOW1 9600
#define OFF_FOW2 13200
#define OFF_FOW3 16800
#define OFF_FRB2 18240
#define OFF_FRB3 18300
#define OFF_PVB2 18320
#define OFF_PVB3 18380
#define OFF_FOB1 18400
#define OFF_FOB2 18460
#define OFF_FOB3 18520
#define OFF_A    18544   // 4*60
#define OFF_APV  18784   // 4*60
#define OFF_CV   19024   // 5*60
#define OFF_C    19324   // 4*60 : [x(20) | Ebar_pp(20) | Ebar_pv(20)] per receiver
#define OFF_H1S  19564   // 4*60
#define OFF_H2S  19804   // 4*60
#define OFF_O    20044   // 4*24 (pad to 96)
#define OFF_STG  20140   // 256*21 staging (stride 21 -> conflict-free)
#define SMEM_FLOATS (OFF_STG + 256 * 21)
#define SMEM_BYTES  (SMEM_FLOATS * 4)      // ~99.7 KB -> 2 CTAs / SM

// -------- packed fp32x2 helpers --------
typedef unsigned long long u64t;

__device__ __forceinline__ u64t pack2(float a, float b) {
    u64t r; asm("mov.b64 %0, {%1, %2};" : "=l"(r) : "f"(a), "f"(b)); return r;
}
__device__ __forceinline__ void unpack2(u64t v, float& a, float& b) {
    asm("mov.b64 {%0, %1}, %2;" : "=f"(a), "=f"(b) : "l"(v));
}
__device__ __forceinline__ u64t fma2(u64t a, u64t b, u64t c) {
    u64t d; asm("fma.rn.f32x2 %0, %1, %2, %3;" : "=l"(d) : "l"(a), "l"(b), "l"(c));
    return d;
}

// ============================================================
// Kernel 1: per-particle / per-vertex first-layer precompute
// ============================================================
__global__ void precompute_kernel(const float* __restrict__ x,
                                  const float* __restrict__ y,
                                  const float* __restrict__ fr_w1,
                                  const float* __restrict__ fr_b1,
                                  const float* __restrict__ pv_w1,
                                  const float* __restrict__ pv_b1)
{
    __shared__ float xb[PDIM * NPART];                 // x[b] slice [p][n]
    __shared__ float yb[SDIM * NVERT];                 // y[b] slice [s][v]
    __shared__ float s_frw[2 * PDIM * HID];            // fr_w1 (40x60)
    __shared__ float s_pvw[(PDIM + SDIM) * HID];       // pv_w1 (34x60)
    __shared__ float s_frb[HID], s_pvb[HID];
    const int b   = blockIdx.x;
    const int tid = threadIdx.x;

    for (int i = tid; i < PDIM * NPART; i += blockDim.x)
        xb[i] = x[(size_t)b * PDIM * NPART + i];
    for (int i = tid; i < SDIM * NVERT; i += blockDim.x)
        yb[i] = y[(size_t)b * SDIM * NVERT + i];
    for (int i = tid; i < 2 * PDIM * HID; i += blockDim.x)
        s_frw[i] = fr_w1[i];
    for (int i = tid; i < (PDIM + SDIM) * HID; i += blockDim.x)
        s_pvw[i] = pv_w1[i];
    for (int i = tid; i < HID; i += blockDim.x) {
        s_frb[i] = fr_b1[i];
        s_pvb[i] = pv_b1[i];
    }
    __syncthreads();

    for (int idx = tid; idx < NPART * HID; idx += blockDim.x) {
        const int n = idx / HID;
        const int h = idx - n * HID;
        float a1 = s_frb[h];
        float a2 = 0.0f;
        float a3 = s_pvb[h];
#pragma unroll
        for (int p = 0; p < PDIM; p++) {
            const float xv = xb[p * NPART + n];     // xt[b][n][p]
            a1 = fmaf(xv, s_frw[p * HID + h], a1);
            a2 = fmaf(xv, s_frw[(PDIM + p) * HID + h], a2);
            a3 = fmaf(xv, s_pvw[p * HID + h], a3);
        }
        const size_t o = (size_t)b * NPART * HID + idx;
        g_A[o]   = a1;
        g_Bv[o]  = a2;
        g_Apv[o] = a3;
    }

    for (int idx = tid; idx < NVERT * HID; idx += blockDim.x) {
        const int v = idx / HID;
        const int h = idx - v * HID;
        float a = 0.0f;
#pragma unroll
        for (int s = 0; s < SDIM; s++)
            a = fmaf(yb[s * NVERT + v], s_pvw[(PDIM + s) * HID + h], a);
        g_Cv[(size_t)b * NVERT * HID + idx] = a;
    }
}

// ============================================================
// MLP layers 2..3 fused j-blockwise (register-lean):
//   for each block of 20 h2 outputs: accumulate over k, relu,
//   immediately fold into the layer-3 accumulator e[20].
// Peak live regs ~ h1[60] + blockacc[20] + eacc[20].
// ============================================================
__device__ __forceinline__ void mlp_tail3(const float* __restrict__ sm,
                                          int w2o, int b2o, int w3o, int b3o,
                                          const float hs[HID], float e[DE])
{
    u64t e2[DE / 2];
    {
        const ulonglong2* bv = reinterpret_cast<const ulonglong2*>(sm + b3o);
#pragma unroll
        for (int j = 0; j < DE / 4; j++) {
            const ulonglong2 v = bv[j];
            e2[2 * j]     = v.x;
            e2[2 * j + 1] = v.y;
        }
    }

#pragma unroll
    for (int jb = 0; jb < 3; jb++) {          // 3 blocks of 20 h2 outputs
        u64t acc[10];
        {
            const ulonglong2* bv =
                reinterpret_cast<const ulonglong2*>(sm + b2o + jb * 20);
#pragma unroll
            for (int i = 0; i < 5; i++) {
                const ulonglong2 v = bv[i];
                acc[2 * i]     = v.x;
                acc[2 * i + 1] = v.y;
            }
        }
#pragma unroll
        for (int k = 0; k < HID; k++) {
            const u64t ap = pack2(hs[k], hs[k]);
            const ulonglong2* wr = reinterpret_cast<const ulonglong2*>(
                sm + w2o + k * HID + jb * 20);
#pragma unroll
            for (int i = 0; i < 5; i++) {
                const ulonglong2 w = wr[i];         // LDS.128 = 4 weights
                acc[2 * i]     = fma2(w.x, ap, acc[2 * i]);
                acc[2 * i + 1] = fma2(w.y, ap, acc[2 * i + 1]);
            }
        }
        // relu + fold this h2 block into e (layer 3 is associative over j)
#pragma unroll
        for (int i = 0; i < 10; i++) {
            float a, b;
            unpack2(acc[i], a, b);
            a = fmaxf(a, 0.0f);
            b = fmaxf(b, 0.0f);
            const int j0 = jb * 20 + 2 * i;
            const u64t ap0 = pack2(a, a);
            const u64t ap1 = pack2(b, b);
            const ulonglong2* w0 = reinterpret_cast<const ulonglong2*>(
                sm + w3o + j0 * DE);
            const ulonglong2* w1 = reinterpret_cast<const ulonglong2*>(
                sm + w3o + (j0 + 1) * DE);
#pragma unroll
            for (int q = 0; q < DE / 4; q++) {
                const ulonglong2 wa = w0[q];
                const ulonglong2 wb = w1[q];
                e2[2 * q]     = fma2(wa.x, ap0, e2[2 * q]);
                e2[2 * q + 1] = fma2(wa.y, ap0, e2[2 * q + 1]);
                e2[2 * q]     = fma2(wb.x, ap1, e2[2 * q]);
                e2[2 * q + 1] = fma2(wb.y, ap1, e2[2 * q + 1]);
            }
        }
    }

#pragma unroll
    for (int j = 0; j < DE / 2; j++) {
        float a, b;
        unpack2(e2[j], a, b);
        e[2 * j]     = fmaxf(a, 0.0f);
        e[2 * j + 1] = fmaxf(b, 0.0f);
    }
}

__device__ __forceinline__ void smem_copy(float* dst, const float* __restrict__ src,
                                          int n, int tid)
{
    for (int i = tid; i < n; i += THREADS) dst[i] = src[i];
}

// ============================================================
// Kernel 2: persistent main kernel. Tile = (batch, 4 receivers)
// 2 CTAs / SM (regs capped at 128, smem ~100 KB each)
// ============================================================
__global__ void __launch_bounds__(THREADS, 2)
main_kernel(const float* __restrict__ x,
            const float* __restrict__ fr_w2, const float* __restrict__ fr_b2,
            const float* __restrict__ fr_w3, const float* __restrict__ fr_b3,
            const float* __restrict__ pv_w2, const float* __restrict__ pv_b2,
            const float* __restrict__ pv_w3, const float* __restrict__ pv_b3,
            const float* __restrict__ fo_w1, const float* __restrict__ fo_b1,
            const float* __restrict__ fo_w2, const float* __restrict__ fo_b2,
            const float* __restrict__ fo_w3, const float* __restrict__ fo_b3)
{
    extern __shared__ float sm[];
    const int t = threadIdx.x;

    // --- load all weights once per block ---
    smem_copy(sm + OFF_FRW2, fr_w2, HID * HID, t);
    smem_copy(sm + OFF_FRW3, fr_w3, HID * DE, t);
    smem_copy(sm + OFF_PVW2, pv_w2, HID * HID, t);
    smem_copy(sm + OFF_PVW3, pv_w3, HID * DE, t);
    smem_copy(sm + OFF_FOW1, fo_w1, HID * HID, t);
    smem_copy(sm + OFF_FOW2, fo_w2, HID * HID, t);
    smem_copy(sm + OFF_FOW3, fo_w3, HID * DOUT, t);
    smem_copy(sm + OFF_FRB2, fr_b2, HID, t);
    smem_copy(sm + OFF_FRB3, fr_b3, DE, t);
    smem_copy(sm + OFF_PVB2, pv_b2, HID, t);
    smem_copy(sm + OFF_PVB3, pv_b3, DE, t);
    smem_copy(sm + OFF_FOB1, fo_b1, HID, t);
    smem_copy(sm + OFF_FOB2, fo_b2, HID, t);
    smem_copy(sm + OFF_FOB3, fo_b3, DOUT, t);
    __syncthreads();

    for (int tile = blockIdx.x; tile < NTILES; tile += gridDim.x) {
        const int b  = tile / NQUAD;
        const int q  = tile - b * NQUAD;
        const int r0 = q * 4;

        // --- stage per-tile inputs ---
        for (int i = t; i < 4 * HID; i += THREADS)
            sm[OFF_A + i] = g_A[((size_t)b * NPART + r0) * HID + i];
        for (int i = t; i < 4 * HID; i += THREADS)
            sm[OFF_APV + i] = g_Apv[((size_t)b * NPART + r0) * HID + i];
        for (int i = t; i < NVERT * HID; i += THREADS)
            sm[OFF_CV + i] = g_Cv[(size_t)b * NVERT * HID + i];
        // xt slice for the 4 receivers: sC[rl][p] = x[b, p, r0+rl]
        for (int i = t; i < 4 * PDIM; i += THREADS) {
            const int rl = i / PDIM;
            const int p  = i - rl * PDIM;
            sm[OFF_C + rl * HID + p] =
                x[(size_t)b * PDIM * NPART + p * NPART + (r0 + rl)];
        }
        __syncthreads();

        // --- edge phase: every thread runs one full edge MLP ---
        {
            float hs[HID];
            int w2o, b2o, w3o, b3o;
            if (t < 236) {                      // fr edges: 4 receivers * 59 senders
                const int rl = t / 59;
                const int i  = t - rl * 59;
                const int r  = r0 + rl;
                const int s  = i + (i >= r ? 1 : 0);
                const float4* av = reinterpret_cast<const float4*>(sm + OFF_A + rl * HID);
                const float4* bv = reinterpret_cast<const float4*>(
                    g_Bv + ((size_t)b * NPART + s) * HID);
#pragma unroll
                for (int k4 = 0; k4 < HID / 4; k4++) {
                    const float4 a4 = av[k4];
                    const float4 b4 = bv[k4];
                    hs[4 * k4 + 0] = fmaxf(a4.x + b4.x, 0.0f);
                    hs[4 * k4 + 1] = fmaxf(a4.y + b4.y, 0.0f);
                    hs[4 * k4 + 2] = fmaxf(a4.z + b4.z, 0.0f);
                    hs[4 * k4 + 3] = fmaxf(a4.w + b4.w, 0.0f);
                }
                w2o = OFF_FRW2; b2o = OFF_FRB2; w3o = OFF_FRW3; b3o = OFF_FRB3;
            } else {                            // pv edges: 4 receivers * 5 vertices
                const int u  = t - 236;
                const int rl = u / NVERT;
                const int v  = u - rl * NVERT;
                const float4* av = reinterpret_cast<const float4*>(sm + OFF_APV + rl * HID);
                const float4* cv = reinterpret_cast<const float4*>(sm + OFF_CV + v * HID);
#pragma unroll
                for (int k4 = 0; k4 < HID / 4; k4++) {
                    const float4 a4 = av[k4];
                    const float4 c4 = cv[k4];
                    hs[4 * k4 + 0] = fmaxf(a4.x + c4.x, 0.0f);
                    hs[4 * k4 + 1] = fmaxf(a4.y + c4.y, 0.0f);
                    hs[4 * k4 + 2] = fmaxf(a4.z + c4.z, 0.0f);
                    hs[4 * k4 + 3] = fmaxf(a4.w + c4.w, 0.0f);
                }
                w2o = OFF_PVW2; b2o = OFF_PVB2; w3o = OFF_PVW3; b3o = OFF_PVB3;
            }

            float e[DE];
            mlp_tail3(sm, w2o, b2o, w3o, b3o, hs, e);
#pragma unroll
            for (int j = 0; j < DE; j++)
                sm[OFF_STG + t * 21 + j] = e[j];
        }
        __syncthreads();

        // --- fixed-order reductions into C = [x | Ebar_pp | Ebar_pv] ---
        if (t < 80) {                   // Ebar_pp: sum 59 fr edges
            const int rl = t / DE;
            const int j  = t - rl * DE;
            float acc = 0.0f;
            for (int i = 0; i < 59; i++)
                acc += sm[OFF_STG + (rl * 59 + i) * 21 + j];
            sm[OFF_C + rl * HID + PDIM + j] = acc;
        } else if (t < 160) {           // Ebar_pv: sum 5 pv edges
            const int u  = t - 80;
            const int rl = u / DE;
            const int j  = u - rl * DE;
            float acc = 0.0f;
#pragma unroll
            for (int v = 0; v < NVERT; v++)
                acc += sm[OFF_STG + (236 + rl * NVERT + v) * 21 + j];
            sm[OFF_C + rl * HID + 2 * PDIM + j] = acc;
        }
        __syncthreads();

        // --- fo MLP, layer 1 (4*60 dot products) ---
        if (t < 4 * HID) {
            const int rl = t / HID;
            const int j  = t - rl * HID;
            float acc = sm[OFF_FOB1 + j];
#pragma unroll
            for (int k = 0; k < HID; k++)
                acc = fmaf(sm[OFF_C + rl * HID + k], sm[OFF_FOW1 + k * HID + j], acc);
            sm[OFF_H1S + t] = fmaxf(acc, 0.0f);
        }
        __syncthreads();

        // --- fo layer 2 ---
        if (t < 4 * HID) {
            const int rl = t / HID;
            const int j  = t - rl * HID;
            float acc = sm[OFF_FOB2 + j];
#pragma unroll
            for (int k = 0; k < HID; k++)
                acc = fmaf(sm[OFF_H1S + rl * HID + k], sm[OFF_FOW2 + k * HID + j], acc);
            sm[OFF_H2S + t] = fmaxf(acc, 0.0f);
        }
        __syncthreads();

        // --- fo layer 3 (4*24 outputs) ---
        if (t < 4 * DOUT) {
            const int rl = t / DOUT;
            const int j  = t - rl * DOUT;
            float acc = sm[OFF_FOB3 + j];
#pragma unroll
            for (int k = 0; k < HID; k++)
                acc = fmaf(sm[OFF_H2S + rl * HID + k], sm[OFF_FOW3 + k * DOUT + j], acc);
            sm[OFF_O + rl * DOUT + j] = fmaxf(acc, 0.0f);
        }
        __syncthreads();

        // --- sum O over the 4 receivers, write partial ---
        if (t < DOUT) {
            const float acc = sm[OFF_O + t] + sm[OFF_O + DOUT + t] +
                              sm[OFF_O + 2 * DOUT + t] + sm[OFF_O + 3 * DOUT + t];
            g_Osum[(size_t)tile * DOUT + t] = acc;
        }
        __syncthreads();   // protect staging/C before next tile overwrites
    }
}

// ============================================================
// Kernel 3: per-batch reduce over 15 tiles + fc head
// ============================================================
__global__ void final_kernel(const float* __restrict__ fc_w,
                             const float* __restrict__ fc_b,
                             float* __restrict__ out)
{
    __shared__ float os[DOUT];
    const int b = blockIdx.x;
    const int t = threadIdx.x;
    if (t < DOUT) {
        float acc = 0.0f;
#pragma unroll
        for (int q = 0; q < NQUAD; q++)
            acc += g_Osum[((size_t)b * NQUAD + q) * DOUT + t];
        os[t] = acc;
    }
    __syncthreads();
    if (t < 2) {
        float acc = fc_b[t];
#pragma unroll
        for (int j = 0; j < DOUT; j++)
            acc = fmaf(os[j], fc_w[j * 2 + t], acc);
        out[b * 2 + t] = acc;
    }
}

// ============================================================
extern "C" void kernel_launch(void* const* d_in, const int* in_sizes, int n_in,
                              void* d_out, int out_size)
{
    const float* x     = (const float*)d_in[0];
    const float* y     = (const float*)d_in[1];
    const float* fr_w1 = (const float*)d_in[2];
    const float* fr_b1 = (const float*)d_in[3];
    const float* fr_w2 = (const float*)d_in[4];
    const float* fr_b2 = (const float*)d_in[5];
    const float* fr_w3 = (const float*)d_in[6];
    const float* fr_b3 = (const float*)d_in[7];
    const float* pv_w1 = (const float*)d_in[8];
    const float* pv_b1 = (const float*)d_in[9];
    const float* pv_w2 = (const float*)d_in[10];
    const float* pv_b2 = (const float*)d_in[11];
    const float* pv_w3 = (const float*)d_in[12];
    const float* pv_b3 = (const float*)d_in[13];
    const float* fo_w1 = (const float*)d_in[14];
    const float* fo_b1 = (const float*)d_in[15];
    const float* fo_w2 = (const float*)d_in[16];
    const float* fo_b2 = (const float*)d_in[17];
    const float* fo_w3 = (const float*)d_in[18];
    const float* fo_b3 = (const float*)d_in[19];
    const float* fc_w  = (const float*)d_in[20];
    const float* fc_b  = (const float*)d_in[21];
    float* out = (float*)d_out;

    precompute_kernel<<<BATCH, THREADS>>>(x, y, fr_w1, fr_b1, pv_w1, pv_b1);

    cudaFuncSetAttribute(main_kernel,
                         cudaFuncAttributeMaxDynamicSharedMemorySize, SMEM_BYTES);
    main_kernel<<<GRID_MAIN, THREADS, SMEM_BYTES>>>(
        x,
        fr_w2, fr_b2, fr_w3, fr_b3,
        pv_w2, pv_b2, pv_w3, pv_b3,
        fo_w1, fo_b1, fo_w2, fo_b2, fo_w3, fo_b3);

    final_kernel<<<BATCH, 32>>>(fc_w, fc_b, out);
}

// round 13
// speedup vs baseline: 1.1056x; 1.0201x over previous
#include <cuda_runtime.h>

#define BATCH 512
#define NPART 60
#define PDIM 20
#define SDIM 14
#define NVERT 5
#define HID 60
#define DE 20
#define DOUT 24
#define NQUAD 15                 // NPART / 4
#define NTILES (BATCH * NQUAD)   // 7680
#define THREADS 256
#define GRID_MAIN 296            // 2 CTAs per SM

// -------- scratch (static device allocation: allowed) --------
__device__ float g_A  [BATCH * NPART * HID];   // fr receiver part + fr_b1
__device__ float g_Bv [BATCH * NPART * HID];   // fr sender part
__device__ float g_Apv[BATCH * NPART * HID];   // pv receiver part + pv_b1
__device__ float g_Cv [BATCH * NVERT * HID];   // pv vertex part
__device__ float g_Osum[NTILES * DOUT];        // per-tile O partial sums

// -------- shared memory layout (float offsets, all 16B aligned) --------
#define OFF_FRW2 0
#define OFF_FRW3 3600
#define OFF_PVW2 4800
#define OFF_PVW3 8400
#define OFF_FOW1 9600
#define OFF_FOW2 13200
#define OFF_B    16800   // staged g_Bv[b]: 60 sender rows x 60  (14.4 KB)
#define OFF_FRB2 20400
#define OFF_FRB3 20460
#define OFF_PVB2 20480
#define OFF_PVB3 20540
#define OFF_FOB1 20560
#define OFF_FOB2 20620
#define OFF_FOB3 20680
#define OFF_A    20704   // 4*60
#define OFF_APV  20944   // 4*60
#define OFF_CV   21184   // 5*60
#define OFF_C    21484   // 4*60 : [x(20) | Ebar_pp(20) | Ebar_pv(20)] per receiver
#define OFF_H1S  21724   // 4*60
#define OFF_H2S  21964   // 4*60
#define OFF_O    22204   // 4*24 (pad to 96)
#define OFF_STG  22300   // 256*21 staging (stride 21 -> conflict-free)
#define SMEM_FLOATS (OFF_STG + 256 * 21)
#define SMEM_BYTES  (SMEM_FLOATS * 4)      // 110704 B = 108.1 KB -> 2 CTAs/SM

// -------- packed fp32x2 helpers --------
typedef unsigned long long u64t;

__device__ __forceinline__ u64t pack2(float a, float b) {
    u64t r; asm("mov.b64 %0, {%1, %2};" : "=l"(r) : "f"(a), "f"(b)); return r;
}
__device__ __forceinline__ void unpack2(u64t v, float& a, float& b) {
    asm("mov.b64 {%0, %1}, %2;" : "=f"(a), "=f"(b) : "l"(v));
}
__device__ __forceinline__ u64t fma2(u64t a, u64t b, u64t c) {
    u64t d; asm("fma.rn.f32x2 %0, %1, %2, %3;" : "=l"(d) : "l"(a), "l"(b), "l"(c));
    return d;
}

// ============================================================
// Kernel 1: per-particle / per-vertex first-layer precompute
// ============================================================
__global__ void precompute_kernel(const float* __restrict__ x,
                                  const float* __restrict__ y,
                                  const float* __restrict__ fr_w1,
                                  const float* __restrict__ fr_b1,
                                  const float* __restrict__ pv_w1,
                                  const float* __restrict__ pv_b1)
{
    __shared__ float xb[PDIM * NPART];                 // x[b] slice [p][n]
    __shared__ float yb[SDIM * NVERT];                 // y[b] slice [s][v]
    __shared__ float s_frw[2 * PDIM * HID];            // fr_w1 (40x60)
    __shared__ float s_pvw[(PDIM + SDIM) * HID];       // pv_w1 (34x60)
    __shared__ float s_frb[HID], s_pvb[HID];
    const int b   = blockIdx.x;
    const int tid = threadIdx.x;

    for (int i = tid; i < PDIM * NPART; i += blockDim.x)
        xb[i] = x[(size_t)b * PDIM * NPART + i];
    for (int i = tid; i < SDIM * NVERT; i += blockDim.x)
        yb[i] = y[(size_t)b * SDIM * NVERT + i];
    for (int i = tid; i < 2 * PDIM * HID; i += blockDim.x)
        s_frw[i] = fr_w1[i];
    for (int i = tid; i < (PDIM + SDIM) * HID; i += blockDim.x)
        s_pvw[i] = pv_w1[i];
    for (int i = tid; i < HID; i += blockDim.x) {
        s_frb[i] = fr_b1[i];
        s_pvb[i] = pv_b1[i];
    }
    __syncthreads();

    for (int idx = tid; idx < NPART * HID; idx += blockDim.x) {
        const int n = idx / HID;
        const int h = idx - n * HID;
        float a1 = s_frb[h];
        float a2 = 0.0f;
        float a3 = s_pvb[h];
#pragma unroll
        for (int p = 0; p < PDIM; p++) {
            const float xv = xb[p * NPART + n];     // xt[b][n][p]
            a1 = fmaf(xv, s_frw[p * HID + h], a1);
            a2 = fmaf(xv, s_frw[(PDIM + p) * HID + h], a2);
            a3 = fmaf(xv, s_pvw[p * HID + h], a3);
        }
        const size_t o = (size_t)b * NPART * HID + idx;
        g_A[o]   = a1;
        g_Bv[o]  = a2;
        g_Apv[o] = a3;
    }

    for (int idx = tid; idx < NVERT * HID; idx += blockDim.x) {
        const int v = idx / HID;
        const int h = idx - v * HID;
        float a = 0.0f;
#pragma unroll
        for (int s = 0; s < SDIM; s++)
            a = fmaf(yb[s * NVERT + v], s_pvw[(PDIM + s) * HID + h], a);
        g_Cv[(size_t)b * NVERT * HID + idx] = a;
    }
}

// ============================================================
// MLP layers 2..3 fused j-blockwise (register-lean), f32x2 FMA
// ============================================================
__device__ __forceinline__ void mlp_tail3(const float* __restrict__ sm,
                                          int w2o, int b2o, int w3o, int b3o,
                                          const float hs[HID], float e[DE])
{
    u64t e2[DE / 2];
    {
        const ulonglong2* bv = reinterpret_cast<const ulonglong2*>(sm + b3o);
#pragma unroll
        for (int j = 0; j < DE / 4; j++) {
            const ulonglong2 v = bv[j];
            e2[2 * j]     = v.x;
            e2[2 * j + 1] = v.y;
        }
    }

#pragma unroll
    for (int jb = 0; jb < 3; jb++) {          // 3 blocks of 20 h2 outputs
        u64t acc[10];
        {
            const ulonglong2* bv =
                reinterpret_cast<const ulonglong2*>(sm + b2o + jb * 20);
#pragma unroll
            for (int i = 0; i < 5; i++) {
                const ulonglong2 v = bv[i];
                acc[2 * i]     = v.x;
                acc[2 * i + 1] = v.y;
            }
        }
#pragma unroll
        for (int k = 0; k < HID; k++) {
            const u64t ap = pack2(hs[k], hs[k]);
            const ulonglong2* wr = reinterpret_cast<const ulonglong2*>(
                sm + w2o + k * HID + jb * 20);
#pragma unroll
            for (int i = 0; i < 5; i++) {
                const ulonglong2 w = wr[i];         // LDS.128 = 4 weights
                acc[2 * i]     = fma2(w.x, ap, acc[2 * i]);
                acc[2 * i + 1] = fma2(w.y, ap, acc[2 * i + 1]);
            }
        }
        // relu + fold this h2 block into e (layer 3 associative over j)
#pragma unroll
        for (int i = 0; i < 10; i++) {
            float a, b;
            unpack2(acc[i], a, b);
            a = fmaxf(a, 0.0f);
            b = fmaxf(b, 0.0f);
            const int j0 = jb * 20 + 2 * i;
            const u64t ap0 = pack2(a, a);
            const u64t ap1 = pack2(b, b);
            const ulonglong2* w0 = reinterpret_cast<const ulonglong2*>(
                sm + w3o + j0 * DE);
            const ulonglong2* w1 = reinterpret_cast<const ulonglong2*>(
                sm + w3o + (j0 + 1) * DE);
#pragma unroll
            for (int q = 0; q < DE / 4; q++) {
                const ulonglong2 wa = w0[q];
                const ulonglong2 wb = w1[q];
                e2[2 * q]     = fma2(wa.x, ap0, e2[2 * q]);
                e2[2 * q + 1] = fma2(wa.y, ap0, e2[2 * q + 1]);
                e2[2 * q]     = fma2(wb.x, ap1, e2[2 * q]);
                e2[2 * q + 1] = fma2(wb.y, ap1, e2[2 * q + 1]);
            }
        }
    }

#pragma unroll
    for (int j = 0; j < DE / 2; j++) {
        float a, b;
        unpack2(e2[j], a, b);
        e[2 * j]     = fmaxf(a, 0.0f);
        e[2 * j + 1] = fmaxf(b, 0.0f);
    }
}

__device__ __forceinline__ void smem_copy(float* dst, const float* __restrict__ src,
                                          int n, int tid)
{
    for (int i = tid; i < n; i += THREADS) dst[i] = src[i];
}

// ============================================================
// Kernel 2: persistent main kernel. Tile = (batch, 4 receivers)
// 2 CTAs / SM; edge phase is 100% SMEM-fed (B tile staged)
// ============================================================
__global__ void __launch_bounds__(THREADS, 2)
main_kernel(const float* __restrict__ x,
            const float* __restrict__ fr_w2, const float* __restrict__ fr_b2,
            const float* __restrict__ fr_w3, const float* __restrict__ fr_b3,
            const float* __restrict__ pv_w2, const float* __restrict__ pv_b2,
            const float* __restrict__ pv_w3, const float* __restrict__ pv_b3,
            const float* __restrict__ fo_w1, const float* __restrict__ fo_b1,
            const float* __restrict__ fo_w2, const float* __restrict__ fo_b2,
            const float* __restrict__ fo_w3, const float* __restrict__ fo_b3)
{
    extern __shared__ float sm[];
    const int t = threadIdx.x;

    // --- load resident weights once per block (fo_w3 stays in gmem/L1) ---
    smem_copy(sm + OFF_FRW2, fr_w2, HID * HID, t);
    smem_copy(sm + OFF_FRW3, fr_w3, HID * DE, t);
    smem_copy(sm + OFF_PVW2, pv_w2, HID * HID, t);
    smem_copy(sm + OFF_PVW3, pv_w3, HID * DE, t);
    smem_copy(sm + OFF_FOW1, fo_w1, HID * HID, t);
    smem_copy(sm + OFF_FOW2, fo_w2, HID * HID, t);
    smem_copy(sm + OFF_FRB2, fr_b2, HID, t);
    smem_copy(sm + OFF_FRB3, fr_b3, DE, t);
    smem_copy(sm + OFF_PVB2, pv_b2, HID, t);
    smem_copy(sm + OFF_PVB3, pv_b3, DE, t);
    smem_copy(sm + OFF_FOB1, fo_b1, HID, t);
    smem_copy(sm + OFF_FOB2, fo_b2, HID, t);
    smem_copy(sm + OFF_FOB3, fo_b3, DOUT, t);
    __syncthreads();

    for (int tile = blockIdx.x; tile < NTILES; tile += gridDim.x) {
        const int b  = tile / NQUAD;
        const int q  = tile - b * NQUAD;
        const int r0 = q * 4;

        // --- stage per-tile inputs (coalesced) ---
        // all 60 sender rows of g_Bv for this batch: 14.4 KB
        {
            const float4* src = reinterpret_cast<const float4*>(
                g_Bv + (size_t)b * NPART * HID);
            float4* dst = reinterpret_cast<float4*>(sm + OFF_B);
            for (int i = t; i < NPART * HID / 4; i += THREADS)
                dst[i] = src[i];
        }
        for (int i = t; i < 4 * HID; i += THREADS)
            sm[OFF_A + i] = g_A[((size_t)b * NPART + r0) * HID + i];
        for (int i = t; i < 4 * HID; i += THREADS)
            sm[OFF_APV + i] = g_Apv[((size_t)b * NPART + r0) * HID + i];
        for (int i = t; i < NVERT * HID; i += THREADS)
            sm[OFF_CV + i] = g_Cv[(size_t)b * NVERT * HID + i];
        // xt slice for the 4 receivers: sC[rl][p] = x[b, p, r0+rl]
        for (int i = t; i < 4 * PDIM; i += THREADS) {
            const int rl = i / PDIM;
            const int p  = i - rl * PDIM;
            sm[OFF_C + rl * HID + p] =
                x[(size_t)b * PDIM * NPART + p * NPART + (r0 + rl)];
        }
        __syncthreads();

        // --- edge phase: every thread runs one full edge MLP, all-SMEM ---
        {
            float hs[HID];
            int w2o, b2o, w3o, b3o;
            if (t < 236) {                      // fr edges: 4 receivers * 59 senders
                const int rl = t / 59;
                const int i  = t - rl * 59;
                const int r  = r0 + rl;
                const int s  = i + (i >= r ? 1 : 0);
                const float4* av = reinterpret_cast<const float4*>(sm + OFF_A + rl * HID);
                const float4* bv = reinterpret_cast<const float4*>(sm + OFF_B + s * HID);
#pragma unroll
                for (int k4 = 0; k4 < HID / 4; k4++) {
                    const float4 a4 = av[k4];
                    const float4 b4 = bv[k4];
                    hs[4 * k4 + 0] = fmaxf(a4.x + b4.x, 0.0f);
                    hs[4 * k4 + 1] = fmaxf(a4.y + b4.y, 0.0f);
                    hs[4 * k4 + 2] = fmaxf(a4.z + b4.z, 0.0f);
                    hs[4 * k4 + 3] = fmaxf(a4.w + b4.w, 0.0f);
                }
                w2o = OFF_FRW2; b2o = OFF_FRB2; w3o = OFF_FRW3; b3o = OFF_FRB3;
            } else {                            // pv edges: 4 receivers * 5 vertices
                const int u  = t - 236;
                const int rl = u / NVERT;
                const int v  = u - rl * NVERT;
                const float4* av = reinterpret_cast<const float4*>(sm + OFF_APV + rl * HID);
                const float4* cv = reinterpret_cast<const float4*>(sm + OFF_CV + v * HID);
#pragma unroll
                for (int k4 = 0; k4 < HID / 4; k4++) {
                    const float4 a4 = av[k4];
                    const float4 c4 = cv[k4];
                    hs[4 * k4 + 0] = fmaxf(a4.x + c4.x, 0.0f);
                    hs[4 * k4 + 1] = fmaxf(a4.y + c4.y, 0.0f);
                    hs[4 * k4 + 2] = fmaxf(a4.z + c4.z, 0.0f);
                    hs[4 * k4 + 3] = fmaxf(a4.w + c4.w, 0.0f);
                }
                w2o = OFF_PVW2; b2o = OFF_PVB2; w3o = OFF_PVW3; b3o = OFF_PVB3;
            }

            float e[DE];
            mlp_tail3(sm, w2o, b2o, w3o, b3o, hs, e);
#pragma unroll
            for (int j = 0; j < DE; j++)
                sm[OFF_STG + t * 21 + j] = e[j];
        }
        __syncthreads();

        // --- fixed-order reductions into C = [x | Ebar_pp | Ebar_pv] ---
        if (t < 80) {                   // Ebar_pp: sum 59 fr edges
            const int rl = t / DE;
            const int j  = t - rl * DE;
            float acc = 0.0f;
            for (int i = 0; i < 59; i++)
                acc += sm[OFF_STG + (rl * 59 + i) * 21 + j];
            sm[OFF_C + rl * HID + PDIM + j] = acc;
        } else if (t < 160) {           // Ebar_pv: sum 5 pv edges
            const int u  = t - 80;
            const int rl = u / DE;
            const int j  = u - rl * DE;
            float acc = 0.0f;
#pragma unroll
            for (int v = 0; v < NVERT; v++)
                acc += sm[OFF_STG + (236 + rl * NVERT + v) * 21 + j];
            sm[OFF_C + rl * HID + 2 * PDIM + j] = acc;
        }
        __syncthreads();

        // --- fo MLP, layer 1 (4*60 dot products) ---
        if (t < 4 * HID) {
            const int rl = t / HID;
            const int j  = t - rl * HID;
            float acc = sm[OFF_FOB1 + j];
#pragma unroll
            for (int k = 0; k < HID; k++)
                acc = fmaf(sm[OFF_C + rl * HID + k], sm[OFF_FOW1 + k * HID + j], acc);
            sm[OFF_H1S + t] = fmaxf(acc, 0.0f);
        }
        __syncthreads();

        // --- fo layer 2 ---
        if (t < 4 * HID) {
            const int rl = t / HID;
            const int j  = t - rl * HID;
            float acc = sm[OFF_FOB2 + j];
#pragma unroll
            for (int k = 0; k < HID; k++)
                acc = fmaf(sm[OFF_H1S + rl * HID + k], sm[OFF_FOW2 + k * HID + j], acc);
            sm[OFF_H2S + t] = fmaxf(acc, 0.0f);
        }
        __syncthreads();

        // --- fo layer 3 (4*24 outputs); fo_w3 via uniform gmem/L1 reads ---
        if (t < 4 * DOUT) {
            const int rl = t / DOUT;
            const int j  = t - rl * DOUT;
            float acc = sm[OFF_FOB3 + j];
#pragma unroll
            for (int k = 0; k < HID; k++)
                acc = fmaf(sm[OFF_H2S + rl * HID + k], fo_w3[k * DOUT + j], acc);
            sm[OFF_O + rl * DOUT + j] = fmaxf(acc, 0.0f);
        }
        __syncthreads();

        // --- sum O over the 4 receivers, write partial ---
        if (t < DOUT) {
            const float acc = sm[OFF_O + t] + sm[OFF_O + DOUT + t] +
                              sm[OFF_O + 2 * DOUT + t] + sm[OFF_O + 3 * DOUT + t];
            g_Osum[(size_t)tile * DOUT + t] = acc;
        }
        __syncthreads();   // protect staging/C/B before next tile overwrites
    }
}

// ============================================================
// Kernel 3: per-batch reduce over 15 tiles + fc head
// ============================================================
__global__ void final_kernel(const float* __restrict__ fc_w,
                             const float* __restrict__ fc_b,
                             float* __restrict__ out)
{
    __shared__ float os[DOUT];
    const int b = blockIdx.x;
    const int t = threadIdx.x;
    if (t < DOUT) {
        float acc = 0.0f;
#pragma unroll
        for (int q = 0; q < NQUAD; q++)
            acc += g_Osum[((size_t)b * NQUAD + q) * DOUT + t];
        os[t] = acc;
    }
    __syncthreads();
    if (t < 2) {
        float acc = fc_b[t];
#pragma unroll
        for (int j = 0; j < DOUT; j++)
            acc = fmaf(os[j], fc_w[j * 2 + t], acc);
        out[b * 2 + t] = acc;
    }
}

// ============================================================
extern "C" void kernel_launch(void* const* d_in, const int* in_sizes, int n_in,
                              void* d_out, int out_size)
{
    const float* x     = (const float*)d_in[0];
    const float* y     = (const float*)d_in[1];
    const float* fr_w1 = (const float*)d_in[2];
    const float* fr_b1 = (const float*)d_in[3];
    const float* fr_w2 = (const float*)d_in[4];
    const float* fr_b2 = (const float*)d_in[5];
    const float* fr_w3 = (const float*)d_in[6];
    const float* fr_b3 = (const float*)d_in[7];
    const float* pv_w1 = (const float*)d_in[8];
    const float* pv_b1 = (const float*)d_in[9];
    const float* pv_w2 = (const float*)d_in[10];
    const float* pv_b2 = (const float*)d_in[11];
    const float* pv_w3 = (const float*)d_in[12];
    const float* pv_b3 = (const float*)d_in[13];
    const float* fo_w1 = (const float*)d_in[14];
    const float* fo_b1 = (const float*)d_in[15];
    const float* fo_w2 = (const float*)d_in[16];
    const float* fo_b2 = (const float*)d_in[17];
    const float* fo_w3 = (const float*)d_in[18];
    const float* fo_b3 = (const float*)d_in[19];
    const float* fc_w  = (const float*)d_in[20];
    const float* fc_b  = (const float*)d_in[21];
    float* out = (float*)d_out;

    precompute_kernel<<<BATCH, THREADS>>>(x, y, fr_w1, fr_b1, pv_w1, pv_b1);

    cudaFuncSetAttribute(main_kernel,
                         cudaFuncAttributeMaxDynamicSharedMemorySize, SMEM_BYTES);
    main_kernel<<<GRID_MAIN, THREADS, SMEM_BYTES>>>(
        x,
        fr_w2, fr_b2, fr_w3, fr_b3,
        pv_w2, pv_b2, pv_w3, pv_b3,
        fo_w1, fo_b1, fo_w2, fo_b2, fo_w3, fo_b3);

    final_kernel<<<BATCH, 32>>>(fc_w, fc_b, out);
}